// round 15
// baseline (speedup 1.0000x reference)
#include <cuda_runtime.h>
#include <stdint.h>

#define NCOLS   24576
#define T1      512
#define EPT1    (NCOLS / (T1 * 4))        // 12 uint4 per thread
#define T2      128
#define NW2     (T2 / 32)                 // 4
#define EPT2    (NCOLS / (T2 * 4))        // 48 uint4 per thread (fallback only)
#define CAPG    384                       // per-row candidate capacity (n~153, sigma~12)
#define MAXROWS 16384
#define HWORDS  2048

// Static candidate floor: 2.5f (key 0xC0200000).
// For N(0,1) rows of 24576: E[count >= 2.5] ~ 153 (sigma ~12); P(n < 64) ~ 3e-13/row,
// P(n > 384) astronomically small. Anything else hits the exact radix fallback in K2.
#define FGUESS  2.5f
#define KGUESS  0xC0200000u

// Global scratch (static __device__ arrays — no allocation)
__device__ unsigned long long g_cand[(size_t)MAXROWS * CAPG];   // composites
__device__ unsigned           g_cnt[MAXROWS];                   // per-row counters

// ---- order-preserving float<->key transform (bigger key = bigger float), branch-free
__device__ __forceinline__ uint32_t f2key(float f) {
    uint32_t b = __float_as_uint(f);
    uint32_t m = (uint32_t)(((int32_t)b) >> 31) | 0x80000000u;  // neg: ~0, pos: 0x80000000
    return b ^ m;
}
__device__ __forceinline__ float key2f(uint32_t k) {
    uint32_t m = (~(uint32_t)(((int32_t)k) >> 31)) | 0x80000000u;
    return __uint_as_float(k ^ m);
}

__device__ __forceinline__ uint4 load_keys(const float4* xin, int pos) {
    float4 v = __ldg(&xin[pos]);
    uint4 kk;
    kk.x = f2key(v.x); kk.y = f2key(v.y); kk.z = f2key(v.z); kk.w = f2key(v.w);
    return kk;
}

// ================= K0: zero the per-row counters =================
__global__ void kzero(int nrows) {
    int i = blockIdx.x * blockDim.x + threadIdx.x;
    if (i < nrows) g_cnt[i] = 0;
}

// ================= K1: pure stream — read + zero output + candidate append ============
// NO barriers, NO shared memory: every warp streams and retires.
__global__ void __launch_bounds__(T1, 3)
k1_stream(const float* __restrict__ x, const int* __restrict__ kptr,
          float* __restrict__ out)
{
    const int row = blockIdx.x;
    const int t   = threadIdx.x;
    const int k   = *kptr;

    const float4* xin  = (const float4*)(x   + (size_t)row * NCOLS);
    float4*       xout = (float4*)      (out + (size_t)row * NCOLS);

    if (k >= NCOLS) {   // copy-through; K2 returns immediately
        #pragma unroll 4
        for (int i = 0; i < EPT1; i++) xout[i * T1 + t] = __ldcs(&xin[i * T1 + t]);
        return;
    }
    if (k <= 0) {       // all zeros; K2 returns immediately
        float4 z = make_float4(0.f, 0.f, 0.f, 0.f);
        #pragma unroll 4
        for (int i = 0; i < EPT1; i++) __stcs(&xout[i * T1 + t], z);
        return;
    }

    // P0: batched loads (front-batched MLP), paired zero-stores, flag math.
    const float4 zero4 = make_float4(0.f, 0.f, 0.f, 0.f);
    uint32_t qmask = 0;
    #pragma unroll 2
    for (int i = 0; i < EPT1; i += 2) {
        float4 v0 = __ldg(&xin[i * T1 + t]);
        float4 v1 = __ldg(&xin[(i + 1) * T1 + t]);
        __stcs(&xout[i * T1 + t],       zero4);
        __stcs(&xout[(i + 1) * T1 + t], zero4);
        float m0 = fmaxf(fmaxf(v0.x, v0.y), fmaxf(v0.z, v0.w));
        float m1 = fmaxf(fmaxf(v1.x, v1.y), fmaxf(v1.z, v1.w));
        qmask |= (m0 >= FGUESS ? 1u : 0u) << i;
        qmask |= (m1 >= FGUESS ? 2u : 0u) << i;
    }

    // P1: revisit flagged quads (~0.15/thread) from L2; append exact composites to global.
    unsigned long long* cand = g_cand + (size_t)row * CAPG;
    while (qmask) {
        int i = __ffs(qmask) - 1;
        qmask &= qmask - 1u;
        uint4 kk = load_keys(xin, i * T1 + t);
        uint32_t base = (uint32_t)(i * T1 + t) * 4u;
        if (kk.x >= KGUESS) { unsigned p = atomicAdd(&g_cnt[row], 1u); if (p < CAPG) cand[p] = ((unsigned long long)kk.x << 16) | (unsigned long long)(0xFFFFu - base); }
        if (kk.y >= KGUESS) { unsigned p = atomicAdd(&g_cnt[row], 1u); if (p < CAPG) cand[p] = ((unsigned long long)kk.y << 16) | (unsigned long long)(0xFFFFu - (base + 1u)); }
        if (kk.z >= KGUESS) { unsigned p = atomicAdd(&g_cnt[row], 1u); if (p < CAPG) cand[p] = ((unsigned long long)kk.z << 16) | (unsigned long long)(0xFFFFu - (base + 2u)); }
        if (kk.w >= KGUESS) { unsigned p = atomicAdd(&g_cnt[row], 1u); if (p < CAPG) cand[p] = ((unsigned long long)kk.w << 16) | (unsigned long long)(0xFFFFu - (base + 3u)); }
    }
}

// ================= K2: per-row select + scatter (tiny) =================

// Block-wide suffix select over histogram h (fallback only): thread t owns bins
// [t*G, t*G+G), G <= 16. Finds bin b = max{b : count(bins >= b) >= rank}.
__device__ __forceinline__ void suffix_select2(
    const uint32_t* h, int G, int nbins, int rank,
    uint32_t* s_wtot, uint32_t* s_sel)
{
    const int t = threadIdx.x, lane = t & 31, warp = t >> 5;
    int v = 0;
    if (t * G < nbins) {
        #pragma unroll
        for (int j = 0; j < 16; j++)
            if (j < G) v += (int)h[t * G + j];
    }
    int s = v;
    #pragma unroll
    for (int d = 1; d < 32; d <<= 1) {
        int o = __shfl_down_sync(0xffffffffu, s, d);
        if (lane + d < 32) s += o;
    }
    if (lane == 0) s_wtot[warp] = (uint32_t)s;
    __syncthreads();
    if (warp == 0) {
        int wv = (lane < NW2) ? (int)s_wtot[lane] : 0;
        int ws = wv;
        #pragma unroll
        for (int d = 1; d < 32; d <<= 1) {
            int o = __shfl_down_sync(0xffffffffu, ws, d);
            if (lane + d < 32) ws += o;
        }
        if (lane < NW2) s_wtot[lane] = (uint32_t)(ws - wv);
    }
    __syncthreads();
    int S = s + (int)s_wtot[warp];
    int above = S - v;
    if (t * G < nbins && S >= rank && above < rank) {
        int cum = above;
        for (int j = G - 1; j >= 0; j--) {
            int c = (int)h[t * G + j];
            if (cum + c >= rank) {
                s_sel[0] = (uint32_t)(t * G + j);
                s_sel[1] = (uint32_t)(rank - cum);
                s_sel[2] = (uint32_t)c;
                break;
            }
            cum += c;
        }
    }
    __syncthreads();
}

__global__ void __launch_bounds__(T2, 8)
k2_select(const float* __restrict__ x, const int* __restrict__ kptr,
          float* __restrict__ out)
{
    __shared__ unsigned long long sc[CAPG];
    __shared__ uint32_t h[HWORDS];
    __shared__ uint32_t s_wtot[NW2];
    __shared__ uint32_t s_sel[4];
    __shared__ uint32_t s_var[4];

    const int row  = blockIdx.x;
    const int t    = threadIdx.x;
    const int lane = t & 31;
    const int k    = *kptr;
    if (k >= NCOLS || k <= 0) return;   // K1 already produced the full output

    const unsigned n = g_cnt[row];
    float* outf = out + (size_t)row * NCOLS;

    if (n >= (unsigned)k && n <= CAPG) {
        // ---- load composites to SMEM ----
        const unsigned long long* cand = g_cand + (size_t)row * CAPG;
        for (unsigned i = t; i < n; i += T2) sc[i] = cand[i];
        __syncthreads();

        // ---- exact k-th by composite (key desc, idx asc): rank count ----
        for (unsigned i = t; i < n; i += T2) {
            unsigned long long cki = sc[i];
            int cnt = 0;
            for (unsigned j = 0; j < n; j++) cnt += (sc[j] > cki);
            if (cnt == k - 1) {   // exactly one winner (composites distinct)
                s_var[0] = (uint32_t)(cki & 0xFFFFFFFFu);
                s_var[1] = (uint32_t)(cki >> 32);
            }
        }
        __syncthreads();
        const unsigned long long cut =
            ((unsigned long long)s_var[1] << 32) | (unsigned long long)s_var[0];

        // ---- scatter exactly-k kept values over K1's zeros ----
        for (unsigned i = t; i < n; i += T2) {
            unsigned long long c = sc[i];
            if (c >= cut) {
                uint32_t idx = 0xFFFFu - (uint32_t)(c & 0xFFFFu);
                outf[idx] = key2f((uint32_t)(c >> 16));
            }
        }
        return;
    }

    // ---------------- FALLBACK: exact 3-pass radix select over the row ----------------
    const float4* xin = (const float4*)(x + (size_t)row * NCOLS);

    // pass 1: key bits [31:21]
    for (int i = t; i < HWORDS; i += T2) h[i] = 0;
    __syncthreads();
    for (int i = 0; i < EPT2; i++) {
        uint4 kk = load_keys(xin, i * T2 + t);
        atomicAdd(&h[kk.x >> 21], 1u);
        atomicAdd(&h[kk.y >> 21], 1u);
        atomicAdd(&h[kk.z >> 21], 1u);
        atomicAdd(&h[kk.w >> 21], 1u);
    }
    __syncthreads();
    suffix_select2(h, 16, 2048, k, s_wtot, s_sel);
    const uint32_t b1 = s_sel[0];
    const int      k1 = (int)s_sel[1];

    // pass 2: key bits [20:10]
    for (int i = t; i < HWORDS; i += T2) h[i] = 0;
    __syncthreads();
    for (int i = 0; i < EPT2; i++) {
        uint4 kk = load_keys(xin, i * T2 + t);
        if ((kk.x >> 21) == b1) atomicAdd(&h[(kk.x >> 10) & 0x7FFu], 1u);
        if ((kk.y >> 21) == b1) atomicAdd(&h[(kk.y >> 10) & 0x7FFu], 1u);
        if ((kk.z >> 21) == b1) atomicAdd(&h[(kk.z >> 10) & 0x7FFu], 1u);
        if ((kk.w >> 21) == b1) atomicAdd(&h[(kk.w >> 10) & 0x7FFu], 1u);
    }
    __syncthreads();
    suffix_select2(h, 16, 2048, k1, s_wtot, s_sel);
    const uint32_t prefix22 = (b1 << 11) | s_sel[0];
    const int      k2       = (int)s_sel[1];

    // pass 3: key bits [9:0]
    for (int i = t; i < HWORDS; i += T2) h[i] = 0;
    __syncthreads();
    for (int i = 0; i < EPT2; i++) {
        uint4 kk = load_keys(xin, i * T2 + t);
        if ((kk.x >> 10) == prefix22) atomicAdd(&h[kk.x & 0x3FFu], 1u);
        if ((kk.y >> 10) == prefix22) atomicAdd(&h[kk.y & 0x3FFu], 1u);
        if ((kk.z >> 10) == prefix22) atomicAdd(&h[kk.z & 0x3FFu], 1u);
        if ((kk.w >> 10) == prefix22) atomicAdd(&h[kk.w & 0x3FFu], 1u);
    }
    __syncthreads();
    suffix_select2(h, 8, 1024, k2, s_wtot, s_sel);
    const uint32_t Tkey = (prefix22 << 10) | s_sel[0];
    const int m    = (int)s_sel[1];
    const int n_eq = (int)s_sel[2];

    uint32_t idx_cut = 0xFFFFFFFFu;
    if (n_eq != m) {
        // counting binary search on index for the tie cut
        int lo = 0, hi = NCOLS - 1;
        while (lo < hi) {
            int mid = (lo + hi) >> 1;
            if (t == 0) s_var[3] = 0;
            __syncthreads();
            int local = 0;
            for (int i = 0; i < EPT2; i++) {
                uint4 kk = load_keys(xin, i * T2 + t);
                int base = (i * T2 + t) * 4;
                local += (kk.x == Tkey && base     <= mid);
                local += (kk.y == Tkey && base + 1 <= mid);
                local += (kk.z == Tkey && base + 2 <= mid);
                local += (kk.w == Tkey && base + 3 <= mid);
            }
            #pragma unroll
            for (int d = 16; d; d >>= 1) local += __shfl_down_sync(0xffffffffu, local, d);
            if (lane == 0 && local) atomicAdd(&s_var[3], (uint32_t)local);
            __syncthreads();
            if ((int)s_var[3] >= m) hi = mid; else lo = mid + 1;
            __syncthreads();
        }
        idx_cut = (uint32_t)lo;
    }

    // fallback output: zeros already in place from K1; store only kept entries
    for (int i = 0; i < EPT2; i++) {
        float4 v = __ldg(&xin[i * T2 + t]);
        uint4 kk;
        kk.x = f2key(v.x); kk.y = f2key(v.y); kk.z = f2key(v.z); kk.w = f2key(v.w);
        uint32_t base = (uint32_t)(i * T2 + t) * 4u;
        if (kk.x > Tkey || (kk.x == Tkey && base      <= idx_cut)) outf[base]      = v.x;
        if (kk.y > Tkey || (kk.y == Tkey && base + 1u <= idx_cut)) outf[base + 1u] = v.y;
        if (kk.z > Tkey || (kk.z == Tkey && base + 2u <= idx_cut)) outf[base + 2u] = v.z;
        if (kk.w > Tkey || (kk.w == Tkey && base + 3u <= idx_cut)) outf[base + 3u] = v.w;
    }
}

extern "C" void kernel_launch(void* const* d_in, const int* in_sizes, int n_in,
                              void* d_out, int out_size)
{
    int xi = 0, ki = 1;
    if (n_in >= 2 && in_sizes[1] > in_sizes[0]) { xi = 1; ki = 0; }

    const float* x  = (const float*)d_in[xi];
    const int*   kp = (const int*)  d_in[ki];
    float*       out = (float*)d_out;

    int nrows = in_sizes[xi] / NCOLS;
    if (nrows > MAXROWS) nrows = MAXROWS;   // scratch bound (dataset: 8192)

    kzero<<<(nrows + 511) / 512, 512>>>(nrows);
    k1_stream<<<nrows, T1>>>(x, kp, out);
    k2_select<<<nrows, T2>>>(x, kp, out);
}

// round 16
// speedup vs baseline: 1.2055x; 1.2055x over previous
#include <cuda_runtime.h>
#include <stdint.h>

#define NCOLS   24576
#define THREADS 512
#define NWARPS  (THREADS / 32)            // 16
#define EPT     (NCOLS / (THREADS * 4))   // 12 uint4 per thread
#define HWORDS  2048                      // hist / candidate region (words)
#define CAP     1000                      // candidate capacity (u64 -> 2000 words <= HWORDS)
// smem words: hist + warp-totals + select-out(4) + vars(8)   (~8.3 KB total)
#define SMEM_WORDS (HWORDS + NWARPS + 4 + 8)
#define SMEM_BYTES (SMEM_WORDS * 4)

// Static candidate floor: 2.6f = 0x40266666 -> key 0xC0266666.
// For N(0,1) rows of 24576: E[count >= 2.6] ~ 115 (sigma ~10.7) -> P(n < 64) ~ 9e-7/row;
// across 8192 rows, ~0.7% chance ONE row takes the exact fallback (correct, just slower).
// Any other distribution (n<k or n>CAP) also lands in the exact radix fallback.
#define FGUESS  2.6f
#define KGUESS  0xC0266666u

// ---- order-preserving float<->key transform (bigger key = bigger float), branch-free
__device__ __forceinline__ uint32_t f2key(float f) {
    uint32_t b = __float_as_uint(f);
    uint32_t m = (uint32_t)(((int32_t)b) >> 31) | 0x80000000u;  // neg: ~0, pos: 0x80000000
    return b ^ m;
}
__device__ __forceinline__ float key2f(uint32_t k) {
    uint32_t m = (~(uint32_t)(((int32_t)k) >> 31)) | 0x80000000u;
    return __uint_as_float(k ^ m);
}

// Block-wide suffix select over histogram h (FALLBACK only): thread t owns bins
// [t*G, t*G+G). Finds bin b = max{b : count(bins >= b) >= rank}; writes
// s_sel[0]=bin, s_sel[1]=rank-within-bin (1-based), s_sel[2]=bin count.
__device__ __forceinline__ void suffix_select(
    const uint32_t* h, int G, int nbins, int rank,
    uint32_t* s_wtot, uint32_t* s_sel)
{
    const int t = threadIdx.x, lane = t & 31, warp = t >> 5;
    int v = 0;
    if (t * G < nbins) {
        #pragma unroll
        for (int j = 0; j < 4; j++)
            if (j < G) v += (int)h[t * G + j];
    }
    int s = v;
    #pragma unroll
    for (int d = 1; d < 32; d <<= 1) {
        int o = __shfl_down_sync(0xffffffffu, s, d);
        if (lane + d < 32) s += o;
    }
    if (lane == 0) s_wtot[warp] = (uint32_t)s;
    __syncthreads();
    if (warp == 0) {
        int wv = (lane < NWARPS) ? (int)s_wtot[lane] : 0;
        int ws = wv;
        #pragma unroll
        for (int d = 1; d < 32; d <<= 1) {
            int o = __shfl_down_sync(0xffffffffu, ws, d);
            if (lane + d < 32) ws += o;
        }
        if (lane < NWARPS) s_wtot[lane] = (uint32_t)(ws - wv);
    }
    __syncthreads();
    int S = s + (int)s_wtot[warp];
    int above = S - v;
    if (t * G < nbins && S >= rank && above < rank) {
        int cum = above;
        for (int j = G - 1; j >= 0; j--) {
            int c = (int)h[t * G + j];
            if (cum + c >= rank) {
                s_sel[0] = (uint32_t)(t * G + j);
                s_sel[1] = (uint32_t)(rank - cum);
                s_sel[2] = (uint32_t)c;
                break;
            }
            cum += c;
        }
    }
    __syncthreads();
}

__device__ __forceinline__ void clear_hist(uint32_t* h) {
    #pragma unroll
    for (int i = 0; i < HWORDS / THREADS; i++) h[i * THREADS + threadIdx.x] = 0;
}

__device__ __forceinline__ uint4 load_keys(const float4* xin, int pos) {
    float4 v = __ldg(&xin[pos]);
    uint4 kk;
    kk.x = f2key(v.x); kk.y = f2key(v.y); kk.z = f2key(v.z); kk.w = f2key(v.w);
    return kk;
}

__global__ void __launch_bounds__(THREADS, 3)
topk_filter_kernel(const float* __restrict__ x, const int* __restrict__ kptr,
                   float* __restrict__ out)
{
    extern __shared__ uint32_t sm[];
    uint32_t* h      = sm;                      // HWORDS (fallback hist / candidate composites)
    uint32_t* s_wtot = h + HWORDS;              // NWARPS
    uint32_t* s_sel  = s_wtot + NWARPS;         // 4
    uint32_t* s_var  = s_sel + 4;               // 8: [0]=cand ctr, [3]=bsearch ctr
    unsigned long long* cand = (unsigned long long*)h;   // CAP u64 composites

    const int t    = threadIdx.x;
    const int lane = t & 31;
    const int k    = *kptr;

    const float4* xin   = (const float4*)(x   + (size_t)blockIdx.x * NCOLS);
    float4*       xout  = (float4*)      (out + (size_t)blockIdx.x * NCOLS);
    float*        outf  = out + (size_t)blockIdx.x * NCOLS;

    if (k >= NCOLS) {
        #pragma unroll 4
        for (int i = 0; i < EPT; i++) xout[i * THREADS + t] = __ldcs(&xin[i * THREADS + t]);
        return;
    }
    if (k <= 0) {
        float4 z = make_float4(0.f, 0.f, 0.f, 0.f);
        #pragma unroll 4
        for (int i = 0; i < EPT; i++) __stcs(&xout[i * THREADS + t], z);
        return;
    }

    if (t == 0) s_var[0] = 0;
    __syncthreads();   // counter visible before any append

    // ---------------- P0: single streaming pass: read + flag mask + ZERO the output ----
    // Two loads issued back-to-back per iteration (front-batched MLP), then the two
    // independent zero-stores, then flag math. Loads allocate in L2 so the flagged-quad
    // revisits in P1 hit L2. The few kept values are scattered in P2.
    const float4 zero4 = make_float4(0.f, 0.f, 0.f, 0.f);
    uint32_t qmask = 0;   // bit i set iff quad i may contain a candidate
    #pragma unroll 2
    for (int i = 0; i < EPT; i += 2) {
        float4 v0 = __ldg(&xin[i * THREADS + t]);
        float4 v1 = __ldg(&xin[(i + 1) * THREADS + t]);
        __stcs(&xout[i * THREADS + t],       zero4);
        __stcs(&xout[(i + 1) * THREADS + t], zero4);
        float m0 = fmaxf(fmaxf(v0.x, v0.y), fmaxf(v0.z, v0.w));
        float m1 = fmaxf(fmaxf(v1.x, v1.y), fmaxf(v1.z, v1.w));
        qmask |= (m0 >= FGUESS ? 1u : 0u) << i;
        qmask |= (m1 >= FGUESS ? 2u : 0u) << i;
    }

    // ---------------- P1: revisit flagged quads (~0.1/thread) from L2; exact keys here
    while (qmask) {
        int i = __ffs(qmask) - 1;
        qmask &= qmask - 1u;
        uint4 kk = load_keys(xin, i * THREADS + t);
        uint32_t base = (uint32_t)(i * THREADS + t) * 4u;
        if (kk.x >= KGUESS) { unsigned p = atomicAdd(&s_var[0], 1u); if (p < CAP) cand[p] = ((unsigned long long)kk.x << 16) | (unsigned long long)(0xFFFFu - base); }
        if (kk.y >= KGUESS) { unsigned p = atomicAdd(&s_var[0], 1u); if (p < CAP) cand[p] = ((unsigned long long)kk.y << 16) | (unsigned long long)(0xFFFFu - (base + 1u)); }
        if (kk.z >= KGUESS) { unsigned p = atomicAdd(&s_var[0], 1u); if (p < CAP) cand[p] = ((unsigned long long)kk.z << 16) | (unsigned long long)(0xFFFFu - (base + 2u)); }
        if (kk.w >= KGUESS) { unsigned p = atomicAdd(&s_var[0], 1u); if (p < CAP) cand[p] = ((unsigned long long)kk.w << 16) | (unsigned long long)(0xFFFFu - (base + 3u)); }
    }
    __syncthreads();   // candidates complete; also orders P0 zero-stores before P2 scatter
    const unsigned n = s_var[0];

    if (n >= (unsigned)k && n <= CAP) {
        // ------------- P2: FUSED rank-count + scatter -------------
        // Composites are distinct, so exactly k of them have rank < k under
        // (key desc, idx asc) order. Each thread writes its winners immediately:
        // no cut broadcast, no extra barrier, no second sweep.
        for (unsigned i = t; i < n; i += THREADS) {
            unsigned long long cki = cand[i];
            int cnt = 0;
            for (unsigned j = 0; j < n; j++) cnt += (cand[j] > cki);
            if (cnt < k) {
                uint32_t idx = 0xFFFFu - (uint32_t)(cki & 0xFFFFu);
                outf[idx] = key2f((uint32_t)(cki >> 16));
            }
        }
        return;
    }

    // ---------------- FALLBACK: exact 3-pass radix select (re-reads from L2) --------
    __syncthreads();
    clear_hist(h);
    __syncthreads();
    #pragma unroll 4
    for (int i = 0; i < EPT; i++) {
        uint4 kk = load_keys(xin, i * THREADS + t);
        atomicAdd(&h[kk.x >> 21], 1u);
        atomicAdd(&h[kk.y >> 21], 1u);
        atomicAdd(&h[kk.z >> 21], 1u);
        atomicAdd(&h[kk.w >> 21], 1u);
    }
    __syncthreads();
    suffix_select(h, 4, 2048, k, s_wtot, s_sel);
    const uint32_t b1 = s_sel[0];
    const int      k1 = (int)s_sel[1];

    clear_hist(h);
    __syncthreads();
    #pragma unroll 4
    for (int i = 0; i < EPT; i++) {
        uint4 kk = load_keys(xin, i * THREADS + t);
        if ((kk.x >> 21) == b1) atomicAdd(&h[(kk.x >> 10) & 0x7FFu], 1u);
        if ((kk.y >> 21) == b1) atomicAdd(&h[(kk.y >> 10) & 0x7FFu], 1u);
        if ((kk.z >> 21) == b1) atomicAdd(&h[(kk.z >> 10) & 0x7FFu], 1u);
        if ((kk.w >> 21) == b1) atomicAdd(&h[(kk.w >> 10) & 0x7FFu], 1u);
    }
    __syncthreads();
    suffix_select(h, 4, 2048, k1, s_wtot, s_sel);
    const uint32_t prefix22 = (b1 << 11) | s_sel[0];
    const int      k2       = (int)s_sel[1];

    clear_hist(h);
    __syncthreads();
    #pragma unroll 4
    for (int i = 0; i < EPT; i++) {
        uint4 kk = load_keys(xin, i * THREADS + t);
        if ((kk.x >> 10) == prefix22) atomicAdd(&h[kk.x & 0x3FFu], 1u);
        if ((kk.y >> 10) == prefix22) atomicAdd(&h[kk.y & 0x3FFu], 1u);
        if ((kk.z >> 10) == prefix22) atomicAdd(&h[kk.z & 0x3FFu], 1u);
        if ((kk.w >> 10) == prefix22) atomicAdd(&h[kk.w & 0x3FFu], 1u);
    }
    __syncthreads();
    suffix_select(h, 2, 1024, k2, s_wtot, s_sel);
    const uint32_t Tkey = (prefix22 << 10) | s_sel[0];
    const int m    = (int)s_sel[1];
    const int n_eq = (int)s_sel[2];

    uint32_t idx_cut = 0xFFFFFFFFu;
    if (n_eq != m) {
        // counting binary search on index for the tie cut
        int lo = 0, hi = NCOLS - 1;
        while (lo < hi) {
            int mid = (lo + hi) >> 1;
            if (t == 0) s_var[3] = 0;
            __syncthreads();
            int local = 0;
            #pragma unroll 4
            for (int i = 0; i < EPT; i++) {
                uint4 kk = load_keys(xin, i * THREADS + t);
                int base = (i * THREADS + t) * 4;
                local += (kk.x == Tkey && base     <= mid);
                local += (kk.y == Tkey && base + 1 <= mid);
                local += (kk.z == Tkey && base + 2 <= mid);
                local += (kk.w == Tkey && base + 3 <= mid);
            }
            #pragma unroll
            for (int d = 16; d; d >>= 1) local += __shfl_down_sync(0xffffffffu, local, d);
            if (lane == 0 && local) atomicAdd(&s_var[3], (uint32_t)local);
            __syncthreads();
            if ((int)s_var[3] >= m) hi = mid; else lo = mid + 1;
            __syncthreads();
        }
        idx_cut = (uint32_t)lo;
    }

    // fallback output: zeros are already in place; store only the kept entries
    #pragma unroll 4
    for (int i = 0; i < EPT; i++) {
        float4 v = __ldg(&xin[i * THREADS + t]);
        uint4 kk;
        kk.x = f2key(v.x); kk.y = f2key(v.y); kk.z = f2key(v.z); kk.w = f2key(v.w);
        uint32_t base = (uint32_t)(i * THREADS + t) * 4u;
        if (kk.x > Tkey || (kk.x == Tkey && base      <= idx_cut)) outf[base]      = v.x;
        if (kk.y > Tkey || (kk.y == Tkey && base + 1u <= idx_cut)) outf[base + 1u] = v.y;
        if (kk.z > Tkey || (kk.z == Tkey && base + 2u <= idx_cut)) outf[base + 2u] = v.z;
        if (kk.w > Tkey || (kk.w == Tkey && base + 3u <= idx_cut)) outf[base + 3u] = v.w;
    }
}

extern "C" void kernel_launch(void* const* d_in, const int* in_sizes, int n_in,
                              void* d_out, int out_size)
{
    int xi = 0, ki = 1;
    if (n_in >= 2 && in_sizes[1] > in_sizes[0]) { xi = 1; ki = 0; }

    const float* x  = (const float*)d_in[xi];
    const int*   kp = (const int*)  d_in[ki];
    float*       out = (float*)d_out;

    int nrows = in_sizes[xi] / NCOLS;

    cudaFuncSetAttribute(topk_filter_kernel,
                         cudaFuncAttributeMaxDynamicSharedMemorySize, SMEM_BYTES);
    topk_filter_kernel<<<nrows, THREADS, SMEM_BYTES>>>(x, kp, out);
}